// round 5
// baseline (speedup 1.0000x reference)
#include <cuda_runtime.h>
#include <math.h>
#include <stdint.h>

// ---------------- problem constants ----------------
#define Bb 4
#define Cc 512
#define NN 4096
#define GG 32
#define CPG 16

// ---------------- scratch (device globals) ----------------
__device__ __align__(128) float g_hT  [(size_t)Bb*NN*Cc];    // [B,N,C] groupnorm out (tf32)
__device__ __align__(128) float g_qkT [(size_t)Bb*NN*2*Cc];  // [B,N,2C]: q|k per token
__device__ __align__(128) float g_v   [(size_t)Bb*Cc*NN];    // [B,C,N]
__device__ __align__(128) float g_aoT [(size_t)Bb*NN*Cc];    // [B,N,C]
__device__ __align__(128) float g_s   [(size_t)Bb*NN*NN];    // [B,N,N] scores/attn
__device__ __align__(128) float g_wr  [4*Cc*Cc];             // tf32 wq|wk|wv|wo
__device__ __align__(128) float g_bqk [2*Cc];                // bq|bk

// ---------------- helpers ----------------
__device__ __forceinline__ uint32_t smem_u32(const void* p) {
    uint32_t a;
    asm("{ .reg .u64 t; cvta.to.shared.u64 t, %1; cvt.u32.u64 %0, t; }" : "=r"(a) : "l"(p));
    return a;
}
__device__ __forceinline__ float rna_tf32(float x) {
    float r; asm("cvt.rna.tf32.f32 %0, %1;" : "=f"(r) : "f"(x)); return r;
}
__device__ __forceinline__ void mma_tf32(float* c, const uint32_t* a, const uint32_t* b) {
    asm volatile("mma.sync.aligned.m16n8k8.row.col.f32.tf32.tf32.f32 "
        "{%0,%1,%2,%3}, {%4,%5,%6,%7}, {%8,%9}, {%0,%1,%2,%3};"
        : "+f"(c[0]), "+f"(c[1]), "+f"(c[2]), "+f"(c[3])
        : "r"(a[0]), "r"(a[1]), "r"(a[2]), "r"(a[3]), "r"(b[0]), "r"(b[1]));
}

// ---------------- block reductions ----------------
__device__ __forceinline__ float block_sum(float v, float* sh) {
    int lane = threadIdx.x & 31, w = threadIdx.x >> 5;
    #pragma unroll
    for (int o = 16; o; o >>= 1) v += __shfl_down_sync(0xffffffffu, v, o);
    if (!lane) sh[w] = v;
    __syncthreads();
    int nw = blockDim.x >> 5;
    v = (threadIdx.x < nw) ? sh[threadIdx.x] : 0.f;
    if (w == 0) {
        #pragma unroll
        for (int o = 16; o; o >>= 1) v += __shfl_down_sync(0xffffffffu, v, o);
        if (!lane) sh[0] = v;
    }
    __syncthreads();
    float r = sh[0]; __syncthreads(); return r;
}
__device__ __forceinline__ float block_max(float v, float* sh) {
    int lane = threadIdx.x & 31, w = threadIdx.x >> 5;
    #pragma unroll
    for (int o = 16; o; o >>= 1) v = fmaxf(v, __shfl_down_sync(0xffffffffu, v, o));
    if (!lane) sh[w] = v;
    __syncthreads();
    int nw = blockDim.x >> 5;
    v = (threadIdx.x < nw) ? sh[threadIdx.x] : -INFINITY;
    if (w == 0) {
        #pragma unroll
        for (int o = 16; o; o >>= 1) v = fmaxf(v, __shfl_down_sync(0xffffffffu, v, o));
        if (!lane) sh[0] = v;
    }
    __syncthreads();
    float r = sh[0]; __syncthreads(); return r;
}

// ---------------- GroupNorm -> token-major hT, tf32-rounded --------------
__global__ __launch_bounds__(256) void groupnorm_kernel(
    const float* __restrict__ x, const float* __restrict__ gamma,
    const float* __restrict__ beta, float* __restrict__ hT)
{
    __shared__ float sh[32];
    int b = blockIdx.x / GG, g = blockIdx.x % GG;
    const size_t base = ((size_t)b * Cc + (size_t)g * CPG) * NN;
    const long len = (long)CPG * NN;

    float s = 0.f, ss = 0.f;
    for (long i = threadIdx.x; i < len; i += 256) {
        float v = x[base + i]; s += v; ss += v * v;
    }
    s  = block_sum(s,  sh);
    ss = block_sum(ss, sh);
    float mean = s / (float)len;
    float var  = ss / (float)len - mean * mean;
    float inv  = rsqrtf(var + 1e-6f);

    float gm[CPG], bt[CPG];
    #pragma unroll
    for (int c = 0; c < CPG; c++) { gm[c] = gamma[g*CPG+c] * inv; bt[c] = beta[g*CPG+c]; }

    for (int i = threadIdx.x; i < NN; i += 256) {
        float vals[CPG];
        #pragma unroll
        for (int c = 0; c < CPG; c++)
            vals[c] = rna_tf32((x[base + (size_t)c*NN + i] - mean) * gm[c] + bt[c]);
        float* dst = hT + ((size_t)b*NN + i) * Cc + g*CPG;
        #pragma unroll
        for (int q = 0; q < CPG/4; q++)
            ((float4*)dst)[q] = make_float4(vals[q*4], vals[q*4+1], vals[q*4+2], vals[q*4+3]);
    }
}

// ---------------- weight rounding + bias concat ----------------
__global__ __launch_bounds__(256) void round_w_kernel(
    const float* __restrict__ a, const float* __restrict__ b,
    const float* __restrict__ c, const float* __restrict__ d,
    float* __restrict__ o)
{
    int i = blockIdx.x * 256 + threadIdx.x;
    int w = i >> 18, j = i & 0x3FFFF;
    const float* src = (w == 0) ? a : (w == 1) ? b : (w == 2) ? c : d;
    o[i] = rna_tf32(src[j]);
}
__global__ __launch_bounds__(256) void concat_bias_kernel(
    const float* __restrict__ a, const float* __restrict__ b, float* __restrict__ o)
{
    int i = blockIdx.x * 256 + threadIdx.x;
    o[i] = (i < Cc) ? a[i] : b[i - Cc];
}

// ---------------- single-pass softmax over rows of [B*N, N] -------------
__global__ __launch_bounds__(256) void softmax_kernel(float* __restrict__ s)
{
    __shared__ float sh[32];
    float* p = s + (size_t)blockIdx.x * NN;
    float v[16];
    #pragma unroll
    for (int t = 0; t < 16; t++) v[t] = p[threadIdx.x + t*256];
    float m = -INFINITY;
    #pragma unroll
    for (int t = 0; t < 16; t++) m = fmaxf(m, v[t]);
    m = block_max(m, sh);
    float sum = 0.f;
    #pragma unroll
    for (int t = 0; t < 16; t++) { v[t] = __expf(v[t] - m); sum += v[t]; }
    sum = block_sum(sum, sh);
    float inv = 1.f / sum;
    #pragma unroll
    for (int t = 0; t < 16; t++) p[threadIdx.x + t*256] = rna_tf32(v[t] * inv);
}

// ---------------- tf32 mma.sync GEMM: D[m,n] = Σk A[m,k] B[n,k] ----------
// CTA tile 128x128x32, 256 threads, warp grid 2(M)x4(N), warp tile 64x32.
// 3-stage cp.async pipeline, 2 CTAs/SM (smem 110.6KB x2 = 221KB, regs <=128).
// EPI: 0 = +bias[n], round tf32   (merged QK proj)
//      1 = +bias[m], round tf32   (V proj)
//      2 = *alpha                 (scores)
//      3 = round tf32             (attn*V)
//      4 = +bias[m] +res          (output proj + residual)
#define BM 128
#define BN 128
#define BK 32
#define STAGES 3
#define LDSROW 36
#define ATILE_F (BM * LDSROW)
#define BTILE_F (BN * LDSROW)
#define STAGE_F (ATILE_F + BTILE_F)
#define SMEM_REQ (STAGES * STAGE_F * 4)

template<int ROWS>
__device__ __forceinline__ void load_tile(const float* g, float* s, int tid, int ld) {
    int cq = (tid & 7) * 4;
    int r0 = tid >> 3;
    #pragma unroll
    for (int i = 0; i < ROWS / 32; i++) {
        int r = r0 + i * 32;
        uint32_t dst = smem_u32(s + r * LDSROW + cq);
        const float* src = g + (size_t)r * ld + cq;
        asm volatile("cp.async.cg.shared.global [%0], [%1], 16;" :: "r"(dst), "l"(src));
    }
}

template<int EPI>
__global__ __launch_bounds__(256, 2) void mma_gemm(
    const float* __restrict__ A, long zA, int ldA,
    const float* __restrict__ B, long zB, int ldB,
    const float* __restrict__ bias,
    const float* __restrict__ res, long zR,
    float* __restrict__ C, long zC, int ldC,
    int K, float alpha)
{
    extern __shared__ float smem[];

    const int tid = threadIdx.x;
    const int m0 = blockIdx.y * BM, n0 = blockIdx.x * BN, bz = blockIdx.z;

    A += (size_t)bz * zA + (size_t)m0 * ldA;
    B += (size_t)bz * zB + (size_t)n0 * ldB;

    const int KT = K / BK;

    #pragma unroll
    for (int st = 0; st < STAGES - 1; st++) {
        load_tile<BM>(A + st * BK, smem + st * STAGE_F, tid, ldA);
        load_tile<BN>(B + st * BK, smem + st * STAGE_F + ATILE_F, tid, ldB);
        asm volatile("cp.async.commit_group;" ::: "memory");
    }

    const int lane = tid & 31, wid = tid >> 5;
    const int gid = lane >> 2, tig = lane & 3;
    const int wm = (wid & 1) * 64;     // warp M offset (2 warps)
    const int wn = (wid >> 1) * 32;    // warp N offset (4 warps)

    float c[4][4][4];
    #pragma unroll
    for (int im = 0; im < 4; im++)
        #pragma unroll
        for (int in = 0; in < 4; in++)
            #pragma unroll
            for (int r = 0; r < 4; r++) c[im][in][r] = 0.f;

    for (int kt = 0; kt < KT; kt++) {
        asm volatile("cp.async.wait_group %0;" :: "n"(STAGES - 2) : "memory");
        __syncthreads();

        if (kt + STAGES - 1 < KT) {
            int st = (kt + STAGES - 1) % STAGES;
            load_tile<BM>(A + (kt + STAGES - 1) * BK, smem + st * STAGE_F, tid, ldA);
            load_tile<BN>(B + (kt + STAGES - 1) * BK, smem + st * STAGE_F + ATILE_F, tid, ldB);
        }
        asm volatile("cp.async.commit_group;" ::: "memory");

        const float* as = smem + (kt % STAGES) * STAGE_F;
        const float* bs = as + ATILE_F;

        #pragma unroll
        for (int k8 = 0; k8 < BK; k8 += 8) {
            uint32_t af[4][4], bf[4][2];
            #pragma unroll
            for (int im = 0; im < 4; im++) {
                const float* p = as + (wm + im*16 + gid) * LDSROW + k8 + tig;
                af[im][0] = __float_as_uint(p[0]);
                af[im][1] = __float_as_uint(p[8 * LDSROW]);
                af[im][2] = __float_as_uint(p[4]);
                af[im][3] = __float_as_uint(p[8 * LDSROW + 4]);
            }
            #pragma unroll
            for (int in = 0; in < 4; in++) {
                const float* p = bs + (wn + in*8 + gid) * LDSROW + k8 + tig;
                bf[in][0] = __float_as_uint(p[0]);
                bf[in][1] = __float_as_uint(p[4]);
            }
            #pragma unroll
            for (int im = 0; im < 4; im++)
                #pragma unroll
                for (int in = 0; in < 4; in++)
                    mma_tf32(c[im][in], af[im], bf[in]);
        }
        __syncthreads();
    }

    // ---- epilogue ----
    float* Cw = C + (size_t)bz * zC + (size_t)(m0 + wm) * ldC + n0 + wn;
    const float* Rw = (EPI == 4) ? res + (size_t)bz * zR + (size_t)(m0 + wm) * ldC + n0 + wn : nullptr;

    #pragma unroll
    for (int im = 0; im < 4; im++) {
        int r0 = im * 16 + gid;
        float bm0 = 0.f, bm1 = 0.f;
        if (EPI == 1 || EPI == 4) {
            bm0 = __ldg(bias + m0 + wm + r0);
            bm1 = __ldg(bias + m0 + wm + r0 + 8);
        }
        #pragma unroll
        for (int in = 0; in < 4; in++) {
            int col = in * 8 + tig * 2;
            float bn0 = 0.f, bn1 = 0.f;
            if (EPI == 0) {
                bn0 = __ldg(bias + n0 + wn + col);
                bn1 = __ldg(bias + n0 + wn + col + 1);
            }
            float v0 = c[im][in][0], v1 = c[im][in][1];
            float v2 = c[im][in][2], v3 = c[im][in][3];
            if (EPI == 0) {
                v0 = rna_tf32(v0 + bn0); v1 = rna_tf32(v1 + bn1);
                v2 = rna_tf32(v2 + bn0); v3 = rna_tf32(v3 + bn1);
            } else if (EPI == 1) {
                v0 = rna_tf32(v0 + bm0); v1 = rna_tf32(v1 + bm0);
                v2 = rna_tf32(v2 + bm1); v3 = rna_tf32(v3 + bm1);
            } else if (EPI == 2) {
                v0 *= alpha; v1 *= alpha; v2 *= alpha; v3 *= alpha;
            } else if (EPI == 3) {
                v0 = rna_tf32(v0); v1 = rna_tf32(v1);
                v2 = rna_tf32(v2); v3 = rna_tf32(v3);
            } else {
                const float* ra = Rw + (size_t)r0 * ldC + col;
                const float* rb = Rw + (size_t)(r0 + 8) * ldC + col;
                v0 += bm0 + ra[0]; v1 += bm0 + ra[1];
                v2 += bm1 + rb[0]; v3 += bm1 + rb[1];
            }
            *(float2*)(Cw + (size_t)r0 * ldC + col)       = make_float2(v0, v1);
            *(float2*)(Cw + (size_t)(r0 + 8) * ldC + col) = make_float2(v2, v3);
        }
    }
}

// ---------------- launch ----------------
extern "C" void kernel_launch(void* const* d_in, const int* in_sizes, int n_in,
                              void* d_out, int out_size)
{
    const float* x     = (const float*)d_in[0];
    const float* gamma = (const float*)d_in[1];
    const float* beta  = (const float*)d_in[2];
    const float* wq    = (const float*)d_in[3];
    const float* bq    = (const float*)d_in[4];
    const float* wk    = (const float*)d_in[5];
    const float* bk    = (const float*)d_in[6];
    const float* wv    = (const float*)d_in[7];
    const float* bv    = (const float*)d_in[8];
    const float* wo    = (const float*)d_in[9];
    const float* bo    = (const float*)d_in[10];
    float* out = (float*)d_out;

    float *hT, *qkT, *v, *aoT, *s, *wr, *bqk;
    cudaGetSymbolAddress((void**)&hT,  g_hT);
    cudaGetSymbolAddress((void**)&qkT, g_qkT);
    cudaGetSymbolAddress((void**)&v,   g_v);
    cudaGetSymbolAddress((void**)&aoT, g_aoT);
    cudaGetSymbolAddress((void**)&s,   g_s);
    cudaGetSymbolAddress((void**)&wr,  g_wr);
    cudaGetSymbolAddress((void**)&bqk, g_bqk);

    static bool attr_done = false;
    if (!attr_done) {
        cudaFuncSetAttribute(mma_gemm<0>, cudaFuncAttributeMaxDynamicSharedMemorySize, SMEM_REQ);
        cudaFuncSetAttribute(mma_gemm<1>, cudaFuncAttributeMaxDynamicSharedMemorySize, SMEM_REQ);
        cudaFuncSetAttribute(mma_gemm<2>, cudaFuncAttributeMaxDynamicSharedMemorySize, SMEM_REQ);
        cudaFuncSetAttribute(mma_gemm<3>, cudaFuncAttributeMaxDynamicSharedMemorySize, SMEM_REQ);
        cudaFuncSetAttribute(mma_gemm<4>, cudaFuncAttributeMaxDynamicSharedMemorySize, SMEM_REQ);
        attr_done = true;
    }

    const long CN  = (long)Cc * NN;      // [C,N] batch stride
    const long NC  = (long)NN * Cc;      // [N,C] batch stride
    const long NC2 = (long)NN * 2 * Cc;  // [N,2C] batch stride
    const long NN2 = (long)NN * NN;
    const float scale = 1.0f / sqrtf((float)Cc);

    // 1) GroupNorm -> hT [B,N,C] (tf32)
    groupnorm_kernel<<<Bb * GG, 256>>>(x, gamma, beta, hT);
    // 2) round weights, concat q/k biases
    round_w_kernel<<<4 * Cc * Cc / 256, 256>>>(wq, wk, wv, wo, wr);
    concat_bias_kernel<<<2 * Cc / 256, 256>>>(bq, bk, bqk);

    // 3) merged QK proj: qkT[i, d] = Σc hT[i,c] (wq|wk)[d,c] + (bq|bk)[d]
    mma_gemm<0><<<dim3(2*Cc/BN, NN/BM, Bb), 256, SMEM_REQ>>>(
        hT, NC, Cc, wr, 0, Cc, bqk, nullptr, 0, qkT, NC2, 2*Cc, Cc, 0.f);
    // 4) v[d,j] = Σc wv[d,c] hT[j,c] + bv[d]
    mma_gemm<1><<<dim3(NN/BN, Cc/BM, Bb), 256, SMEM_REQ>>>(
        wr + 2*Cc*Cc, 0, Cc, hT, NC, Cc, bv, nullptr, 0, v, CN, NN, Cc, 0.f);
    // 5) scores[i,j] = scale * Σc q[i,c] k[j,c]   (q = qkT[:, :512], k = qkT[:, 512:])
    mma_gemm<2><<<dim3(NN/BN, NN/BM, Bb), 256, SMEM_REQ>>>(
        qkT, NC2, 2*Cc, qkT + Cc, NC2, 2*Cc, nullptr, nullptr, 0, s, NN2, NN, Cc, scale);
    // 6) softmax rows (tf32-rounded output)
    softmax_kernel<<<Bb * NN, 256>>>(s);
    // 7) aoT[i,c] = Σj attn[i,j] v[c,j]
    mma_gemm<3><<<dim3(Cc/BN, NN/BM, Bb), 256, SMEM_REQ>>>(
        s, NN2, NN, v, CN, NN, nullptr, nullptr, 0, aoT, NC, Cc, NN, 0.f);
    // 8) out[c,i] = x[c,i] + Σd wo[c,d] aoT[i,d] + bo[c]
    mma_gemm<4><<<dim3(NN/BN, Cc/BM, Bb), 256, SMEM_REQ>>>(
        wr + 3*Cc*Cc, 0, Cc, aoT, NC, Cc, bo, x, CN, out, CN, NN, Cc, 0.f);
}

// round 6
// speedup vs baseline: 1.7913x; 1.7913x over previous
#include <cuda_runtime.h>
#include <cuda_bf16.h>
#include <math.h>
#include <stdint.h>

typedef __nv_bfloat16 bf16;
typedef __nv_bfloat162 bf162;

// ---------------- problem constants ----------------
#define Bb 4
#define Cc 512
#define NN 4096
#define GG 32
#define CPG 16

// ---------------- scratch (device globals) ----------------
__device__ __align__(128) bf16  g_h16  [(size_t)Bb*NN*Cc];    // [B,N,C] GN out
__device__ __align__(128) bf16  g_qk16 [(size_t)Bb*NN*2*Cc];  // [B,N,2C] q|k
__device__ __align__(128) bf16  g_v16  [(size_t)Bb*Cc*NN];    // [B,C,N]
__device__ __align__(128) bf16  g_ao16 [(size_t)Bb*NN*Cc];    // [B,N,C]
__device__ __align__(128) float g_s    [(size_t)Bb*NN*NN];    // [B,N,N] scores fp32
__device__ __align__(128) bf16  g_a16  [(size_t)Bb*NN*NN];    // [B,N,N] attn bf16
__device__ __align__(128) bf16  g_w16  [4*Cc*Cc];             // wq|wk|wv|wo
__device__ __align__(128) float g_bqk  [2*Cc];                // bq|bk

// ---------------- helpers ----------------
__device__ __forceinline__ uint32_t smem_u32(const void* p) {
    uint32_t a;
    asm("{ .reg .u64 t; cvta.to.shared.u64 t, %1; cvt.u32.u64 %0, t; }" : "=r"(a) : "l"(p));
    return a;
}
__device__ __forceinline__ void mma_bf16(float* c, const uint32_t* a, const uint32_t* b) {
    asm volatile("mma.sync.aligned.m16n8k16.row.col.f32.bf16.bf16.f32 "
        "{%0,%1,%2,%3}, {%4,%5,%6,%7}, {%8,%9}, {%0,%1,%2,%3};"
        : "+f"(c[0]), "+f"(c[1]), "+f"(c[2]), "+f"(c[3])
        : "r"(a[0]), "r"(a[1]), "r"(a[2]), "r"(a[3]), "r"(b[0]), "r"(b[1]));
}

// ---------------- block reductions ----------------
__device__ __forceinline__ float block_sum(float v, float* sh) {
    int lane = threadIdx.x & 31, w = threadIdx.x >> 5;
    #pragma unroll
    for (int o = 16; o; o >>= 1) v += __shfl_down_sync(0xffffffffu, v, o);
    if (!lane) sh[w] = v;
    __syncthreads();
    int nw = blockDim.x >> 5;
    v = (threadIdx.x < nw) ? sh[threadIdx.x] : 0.f;
    if (w == 0) {
        #pragma unroll
        for (int o = 16; o; o >>= 1) v += __shfl_down_sync(0xffffffffu, v, o);
        if (!lane) sh[0] = v;
    }
    __syncthreads();
    float r = sh[0]; __syncthreads(); return r;
}
__device__ __forceinline__ float block_max(float v, float* sh) {
    int lane = threadIdx.x & 31, w = threadIdx.x >> 5;
    #pragma unroll
    for (int o = 16; o; o >>= 1) v = fmaxf(v, __shfl_down_sync(0xffffffffu, v, o));
    if (!lane) sh[w] = v;
    __syncthreads();
    int nw = blockDim.x >> 5;
    v = (threadIdx.x < nw) ? sh[threadIdx.x] : -INFINITY;
    if (w == 0) {
        #pragma unroll
        for (int o = 16; o; o >>= 1) v = fmaxf(v, __shfl_down_sync(0xffffffffu, v, o));
        if (!lane) sh[0] = v;
    }
    __syncthreads();
    float r = sh[0]; __syncthreads(); return r;
}

// ---------------- GroupNorm -> token-major bf16 hT --------------
__global__ __launch_bounds__(256) void groupnorm_kernel(
    const float* __restrict__ x, const float* __restrict__ gamma,
    const float* __restrict__ beta, bf16* __restrict__ hT)
{
    __shared__ float sh[32];
    int b = blockIdx.x / GG, g = blockIdx.x % GG;
    const size_t base = ((size_t)b * Cc + (size_t)g * CPG) * NN;
    const long len = (long)CPG * NN;

    float s = 0.f, ss = 0.f;
    for (long i = threadIdx.x; i < len; i += 256) {
        float v = x[base + i]; s += v; ss += v * v;
    }
    s  = block_sum(s,  sh);
    ss = block_sum(ss, sh);
    float mean = s / (float)len;
    float var  = ss / (float)len - mean * mean;
    float inv  = rsqrtf(var + 1e-6f);

    float gm[CPG], bt[CPG];
    #pragma unroll
    for (int c = 0; c < CPG; c++) { gm[c] = gamma[g*CPG+c] * inv; bt[c] = beta[g*CPG+c]; }

    for (int i = threadIdx.x; i < NN; i += 256) {
        bf162 vals[CPG/2];
        #pragma unroll
        for (int c = 0; c < CPG; c += 2) {
            float a = (x[base + (size_t)c*NN + i] - mean) * gm[c] + bt[c];
            float b2 = (x[base + (size_t)(c+1)*NN + i] - mean) * gm[c+1] + bt[c+1];
            vals[c/2] = __floats2bfloat162_rn(a, b2);
        }
        bf16* dst = hT + ((size_t)b*NN + i) * Cc + g*CPG;
        #pragma unroll
        for (int q = 0; q < CPG/8; q++)
            ((float4*)dst)[q] = *(float4*)&vals[q*4];
    }
}

// ---------------- weight convert + bias concat ----------------
__global__ __launch_bounds__(256) void round_w_kernel(
    const float* __restrict__ a, const float* __restrict__ b,
    const float* __restrict__ c, const float* __restrict__ d,
    bf16* __restrict__ o)
{
    int i = blockIdx.x * 256 + threadIdx.x;
    int w = i >> 18, j = i & 0x3FFFF;
    const float* src = (w == 0) ? a : (w == 1) ? b : (w == 2) ? c : d;
    o[i] = __float2bfloat16_rn(src[j]);
}
__global__ __launch_bounds__(256) void concat_bias_kernel(
    const float* __restrict__ a, const float* __restrict__ b, float* __restrict__ o)
{
    int i = blockIdx.x * 256 + threadIdx.x;
    o[i] = (i < Cc) ? a[i] : b[i - Cc];
}

// ---------------- softmax: fp32 scores in -> bf16 attn out -------------
__global__ __launch_bounds__(256) void softmax_kernel(
    const float* __restrict__ s, bf16* __restrict__ a)
{
    __shared__ float sh[32];
    const float* p = s + (size_t)blockIdx.x * NN;
    bf16* pa = a + (size_t)blockIdx.x * NN;
    float v[16];
    #pragma unroll
    for (int t = 0; t < 16; t++) v[t] = p[threadIdx.x + t*256];
    float m = -INFINITY;
    #pragma unroll
    for (int t = 0; t < 16; t++) m = fmaxf(m, v[t]);
    m = block_max(m, sh);
    float sum = 0.f;
    #pragma unroll
    for (int t = 0; t < 16; t++) { v[t] = __expf(v[t] - m); sum += v[t]; }
    sum = block_sum(sum, sh);
    float inv = 1.f / sum;
    #pragma unroll
    for (int t = 0; t < 16; t++) pa[threadIdx.x + t*256] = __float2bfloat16_rn(v[t] * inv);
}

// ---------------- bf16 mma.sync GEMM: D[m,n] = Σk A[m,k] B[n,k] ----------
// CTA tile 128x128x64(bf16), 256 threads, warp grid 2(M)x4(N), warp tile 64x32.
// 3-stage cp.async pipeline, 2 CTAs/SM. Smem row = 72 bf16 (conflict-free frags).
// EPI: 0 = +bias[n] -> bf16   (merged QK proj)
//      1 = +bias[m] -> bf16   (V proj)
//      2 = *alpha  -> fp32    (scores)
//      3 = -> bf16            (attn*V)
//      4 = +bias[m]+res fp32  (output proj + residual)
#define BM 128
#define BN 128
#define BK 64
#define STAGES 3
#define SROW 72                       // bf16 per smem row
#define SROW_W 36                     // words per smem row
#define ATILE_H (BM * SROW)           // bf16 elems
#define BTILE_H (BN * SROW)
#define STAGE_H (ATILE_H + BTILE_H)
#define SMEM_REQ (STAGES * STAGE_H * 2)

template<int ROWS>
__device__ __forceinline__ void load_tile(const bf16* g, bf16* s, int tid, int ld) {
    int ch = tid & 7;                 // 8 x 16B chunks per 64-bf16 row
    int r0 = tid >> 3;                // 32 rows per pass
    #pragma unroll
    for (int i = 0; i < ROWS / 32; i++) {
        int r = r0 + i * 32;
        uint32_t dst = smem_u32(s + r * SROW + ch * 8);
        const bf16* src = g + (size_t)r * ld + ch * 8;
        asm volatile("cp.async.cg.shared.global [%0], [%1], 16;" :: "r"(dst), "l"(src));
    }
}

template<int EPI>
__global__ __launch_bounds__(256, 2) void mma_gemm(
    const bf16* __restrict__ A, long zA, int ldA,
    const bf16* __restrict__ B, long zB, int ldB,
    const float* __restrict__ bias,
    const float* __restrict__ res, long zR,
    void* __restrict__ Cout, long zC, int ldC,
    int K, float alpha)
{
    constexpr bool OUT_BF = (EPI == 0 || EPI == 1 || EPI == 3);
    extern __shared__ bf16 smem[];

    const int tid = threadIdx.x;
    const int m0 = blockIdx.y * BM, n0 = blockIdx.x * BN, bz = blockIdx.z;

    A += (size_t)bz * zA + (size_t)m0 * ldA;
    B += (size_t)bz * zB + (size_t)n0 * ldB;

    const int KT = K / BK;

    #pragma unroll
    for (int st = 0; st < STAGES - 1; st++) {
        load_tile<BM>(A + st * BK, smem + st * STAGE_H, tid, ldA);
        load_tile<BN>(B + st * BK, smem + st * STAGE_H + ATILE_H, tid, ldB);
        asm volatile("cp.async.commit_group;" ::: "memory");
    }

    const int lane = tid & 31, wid = tid >> 5;
    const int gid = lane >> 2, tig = lane & 3;
    const int wm = (wid & 1) * 64;
    const int wn = (wid >> 1) * 32;

    float c[4][4][4];
    #pragma unroll
    for (int im = 0; im < 4; im++)
        #pragma unroll
        for (int in = 0; in < 4; in++)
            #pragma unroll
            for (int r = 0; r < 4; r++) c[im][in][r] = 0.f;

    for (int kt = 0; kt < KT; kt++) {
        asm volatile("cp.async.wait_group %0;" :: "n"(STAGES - 2) : "memory");
        __syncthreads();

        if (kt + STAGES - 1 < KT) {
            int st = (kt + STAGES - 1) % STAGES;
            load_tile<BM>(A + (kt + STAGES - 1) * BK, smem + st * STAGE_H, tid, ldA);
            load_tile<BN>(B + (kt + STAGES - 1) * BK, smem + st * STAGE_H + ATILE_H, tid, ldB);
        }
        asm volatile("cp.async.commit_group;" ::: "memory");

        const uint32_t* as = (const uint32_t*)(smem + (kt % STAGES) * STAGE_H);
        const uint32_t* bs = (const uint32_t*)(smem + (kt % STAGES) * STAGE_H + ATILE_H);

        #pragma unroll
        for (int kk = 0; kk < 4; kk++) {          // 4 x k16 per BK=64
            uint32_t af[4][4], bf[4][2];
            #pragma unroll
            for (int im = 0; im < 4; im++) {
                const uint32_t* p = as + (wm + im*16 + gid) * SROW_W + kk*8 + tig;
                af[im][0] = p[0];
                af[im][1] = p[8 * SROW_W];
                af[im][2] = p[4];
                af[im][3] = p[8 * SROW_W + 4];
            }
            #pragma unroll
            for (int in = 0; in < 4; in++) {
                const uint32_t* p = bs + (wn + in*8 + gid) * SROW_W + kk*8 + tig;
                bf[in][0] = p[0];
                bf[in][1] = p[4];
            }
            #pragma unroll
            for (int im = 0; im < 4; im++)
                #pragma unroll
                for (int in = 0; in < 4; in++)
                    mma_bf16(c[im][in], af[im], bf[in]);
        }
        __syncthreads();
    }

    // ---- epilogue ----
    #pragma unroll
    for (int im = 0; im < 4; im++) {
        int r0 = im * 16 + gid;
        float bm0 = 0.f, bm1 = 0.f;
        if (EPI == 1 || EPI == 4) {
            bm0 = __ldg(bias + m0 + wm + r0);
            bm1 = __ldg(bias + m0 + wm + r0 + 8);
        }
        #pragma unroll
        for (int in = 0; in < 4; in++) {
            int col = in * 8 + tig * 2;
            float v0 = c[im][in][0], v1 = c[im][in][1];
            float v2 = c[im][in][2], v3 = c[im][in][3];
            if (EPI == 0) {
                float bn0 = __ldg(bias + n0 + wn + col);
                float bn1 = __ldg(bias + n0 + wn + col + 1);
                v0 += bn0; v1 += bn1; v2 += bn0; v3 += bn1;
            } else if (EPI == 1) {
                v0 += bm0; v1 += bm0; v2 += bm1; v3 += bm1;
            } else if (EPI == 2) {
                v0 *= alpha; v1 *= alpha; v2 *= alpha; v3 *= alpha;
            } else if (EPI == 4) {
                const float* ra = res + (size_t)bz * zR + (size_t)(m0 + wm + r0) * ldC + n0 + wn + col;
                const float* rb = res + (size_t)bz * zR + (size_t)(m0 + wm + r0 + 8) * ldC + n0 + wn + col;
                v0 += bm0 + ra[0]; v1 += bm0 + ra[1];
                v2 += bm1 + rb[0]; v3 += bm1 + rb[1];
            }
            if (OUT_BF) {
                bf16* Cb = (bf16*)Cout + (size_t)bz * zC + (size_t)(m0 + wm + r0) * ldC + n0 + wn + col;
                bf16* Cb2 = (bf16*)Cout + (size_t)bz * zC + (size_t)(m0 + wm + r0 + 8) * ldC + n0 + wn + col;
                *(bf162*)Cb  = __floats2bfloat162_rn(v0, v1);
                *(bf162*)Cb2 = __floats2bfloat162_rn(v2, v3);
            } else {
                float* Cf = (float*)Cout + (size_t)bz * zC + (size_t)(m0 + wm + r0) * ldC + n0 + wn + col;
                float* Cf2 = (float*)Cout + (size_t)bz * zC + (size_t)(m0 + wm + r0 + 8) * ldC + n0 + wn + col;
                *(float2*)Cf  = make_float2(v0, v1);
                *(float2*)Cf2 = make_float2(v2, v3);
            }
        }
    }
}

// ---------------- launch ----------------
extern "C" void kernel_launch(void* const* d_in, const int* in_sizes, int n_in,
                              void* d_out, int out_size)
{
    const float* x     = (const float*)d_in[0];
    const float* gamma = (const float*)d_in[1];
    const float* beta  = (const float*)d_in[2];
    const float* wq    = (const float*)d_in[3];
    const float* bq    = (const float*)d_in[4];
    const float* wk    = (const float*)d_in[5];
    const float* bk    = (const float*)d_in[6];
    const float* wv    = (const float*)d_in[7];
    const float* bv    = (const float*)d_in[8];
    const float* wo    = (const float*)d_in[9];
    const float* bo    = (const float*)d_in[10];
    float* out = (float*)d_out;

    bf16 *h16, *qk16, *v16, *ao16, *a16, *w16;
    float *s, *bqk;
    cudaGetSymbolAddress((void**)&h16,  g_h16);
    cudaGetSymbolAddress((void**)&qk16, g_qk16);
    cudaGetSymbolAddress((void**)&v16,  g_v16);
    cudaGetSymbolAddress((void**)&ao16, g_ao16);
    cudaGetSymbolAddress((void**)&a16,  g_a16);
    cudaGetSymbolAddress((void**)&w16,  g_w16);
    cudaGetSymbolAddress((void**)&s,    g_s);
    cudaGetSymbolAddress((void**)&bqk,  g_bqk);

    static bool attr_done = false;
    if (!attr_done) {
        cudaFuncSetAttribute(mma_gemm<0>, cudaFuncAttributeMaxDynamicSharedMemorySize, SMEM_REQ);
        cudaFuncSetAttribute(mma_gemm<1>, cudaFuncAttributeMaxDynamicSharedMemorySize, SMEM_REQ);
        cudaFuncSetAttribute(mma_gemm<2>, cudaFuncAttributeMaxDynamicSharedMemorySize, SMEM_REQ);
        cudaFuncSetAttribute(mma_gemm<3>, cudaFuncAttributeMaxDynamicSharedMemorySize, SMEM_REQ);
        cudaFuncSetAttribute(mma_gemm<4>, cudaFuncAttributeMaxDynamicSharedMemorySize, SMEM_REQ);
        attr_done = true;
    }

    const long CN  = (long)Cc * NN;      // [C,N] batch stride
    const long NC  = (long)NN * Cc;      // [N,C] batch stride
    const long NC2 = (long)NN * 2 * Cc;  // [N,2C] batch stride
    const long NN2 = (long)NN * NN;
    const float scale = 1.0f / sqrtf((float)Cc);

    // 1) GroupNorm -> h16 [B,N,C]
    groupnorm_kernel<<<Bb * GG, 256>>>(x, gamma, beta, h16);
    // 2) weights -> bf16, concat q/k biases
    round_w_kernel<<<4 * Cc * Cc / 256, 256>>>(wq, wk, wv, wo, w16);
    concat_bias_kernel<<<2 * Cc / 256, 256>>>(bq, bk, bqk);

    // 3) merged QK proj: qk16[i,d] = Σc h16[i,c] (wq|wk)[d,c] + (bq|bk)[d]
    mma_gemm<0><<<dim3(2*Cc/BN, NN/BM, Bb), 256, SMEM_REQ>>>(
        h16, NC, Cc, w16, 0, Cc, bqk, nullptr, 0, qk16, NC2, 2*Cc, Cc, 0.f);
    // 4) v16[d,j] = Σc wv[d,c] h16[j,c] + bv[d]
    mma_gemm<1><<<dim3(NN/BN, Cc/BM, Bb), 256, SMEM_REQ>>>(
        w16 + 2*Cc*Cc, 0, Cc, h16, NC, Cc, bv, nullptr, 0, v16, CN, NN, Cc, 0.f);
    // 5) scores[i,j] = scale * Σc q[i,c] k[j,c]  (fp32 out)
    mma_gemm<2><<<dim3(NN/BN, NN/BM, Bb), 256, SMEM_REQ>>>(
        qk16, NC2, 2*Cc, qk16 + Cc, NC2, 2*Cc, nullptr, nullptr, 0, s, NN2, NN, Cc, scale);
    // 6) softmax rows: fp32 scores -> bf16 attn
    softmax_kernel<<<Bb * NN, 256>>>(s, a16);
    // 7) ao16[i,c] = Σj attn[i,j] v16[c,j]
    mma_gemm<3><<<dim3(Cc/BN, NN/BM, Bb), 256, SMEM_REQ>>>(
        a16, NN2, NN, v16, CN, NN, nullptr, nullptr, 0, ao16, NC, Cc, NN, 0.f);
    // 8) out[c,i] = x[c,i] + Σd wo[c,d] ao16[i,d] + bo[c]  (fp32 out)
    mma_gemm<4><<<dim3(NN/BN, Cc/BM, Bb), 256, SMEM_REQ>>>(
        w16 + 3*Cc*Cc, 0, Cc, ao16, NC, Cc, bo, x, CN, out, CN, NN, Cc, 0.f);
}

// round 7
// speedup vs baseline: 1.8740x; 1.0462x over previous
#include <cuda_runtime.h>
#include <cuda_bf16.h>
#include <math.h>
#include <stdint.h>

typedef __nv_bfloat16 bf16;
typedef __nv_bfloat162 bf162;

// ---------------- problem constants ----------------
#define Bb 4
#define Cc 512
#define NN 4096
#define GG 32
#define CPG 16

// ---------------- scratch (device globals) ----------------
__device__ __align__(128) bf16  g_h16  [(size_t)Bb*NN*Cc];    // [B,N,C] GN out
__device__ __align__(128) bf16  g_qk16 [(size_t)Bb*NN*2*Cc];  // [B,N,2C] q|k
__device__ __align__(128) bf16  g_v16  [(size_t)Bb*Cc*NN];    // [B,C,N]
__device__ __align__(128) bf16  g_ao16 [(size_t)Bb*NN*Cc];    // [B,N,C]
__device__ __align__(128) float g_s    [(size_t)Bb*NN*NN];    // [B,N,N] scores fp32
__device__ __align__(128) bf16  g_a16  [(size_t)Bb*NN*NN];    // [B,N,N] attn bf16
__device__ __align__(128) bf16  g_w16  [4*Cc*Cc];             // wq|wk|wv|wo
__device__ __align__(128) float g_bqk  [2*Cc];                // bq|bk

// ---------------- helpers ----------------
__device__ __forceinline__ uint32_t smem_u32(const void* p) {
    uint32_t a;
    asm("{ .reg .u64 t; cvta.to.shared.u64 t, %1; cvt.u32.u64 %0, t; }" : "=r"(a) : "l"(p));
    return a;
}
__device__ __forceinline__ void mma_bf16(float* c, const uint32_t* a, const uint32_t* b) {
    asm volatile("mma.sync.aligned.m16n8k16.row.col.f32.bf16.bf16.f32 "
        "{%0,%1,%2,%3}, {%4,%5,%6,%7}, {%8,%9}, {%0,%1,%2,%3};"
        : "+f"(c[0]), "+f"(c[1]), "+f"(c[2]), "+f"(c[3])
        : "r"(a[0]), "r"(a[1]), "r"(a[2]), "r"(a[3]), "r"(b[0]), "r"(b[1]));
}
__device__ __forceinline__ void ldmatrix_x4(uint32_t* r, uint32_t addr) {
    asm volatile("ldmatrix.sync.aligned.m8n8.x4.shared.b16 {%0,%1,%2,%3}, [%4];"
        : "=r"(r[0]), "=r"(r[1]), "=r"(r[2]), "=r"(r[3]) : "r"(addr));
}

// ---------------- block reductions ----------------
__device__ __forceinline__ float block_sum(float v, float* sh) {
    int lane = threadIdx.x & 31, w = threadIdx.x >> 5;
    #pragma unroll
    for (int o = 16; o; o >>= 1) v += __shfl_down_sync(0xffffffffu, v, o);
    if (!lane) sh[w] = v;
    __syncthreads();
    int nw = blockDim.x >> 5;
    v = (threadIdx.x < nw) ? sh[threadIdx.x] : 0.f;
    if (w == 0) {
        #pragma unroll
        for (int o = 16; o; o >>= 1) v += __shfl_down_sync(0xffffffffu, v, o);
        if (!lane) sh[0] = v;
    }
    __syncthreads();
    float r = sh[0]; __syncthreads(); return r;
}
__device__ __forceinline__ float block_max(float v, float* sh) {
    int lane = threadIdx.x & 31, w = threadIdx.x >> 5;
    #pragma unroll
    for (int o = 16; o; o >>= 1) v = fmaxf(v, __shfl_down_sync(0xffffffffu, v, o));
    if (!lane) sh[w] = v;
    __syncthreads();
    int nw = blockDim.x >> 5;
    v = (threadIdx.x < nw) ? sh[threadIdx.x] : -INFINITY;
    if (w == 0) {
        #pragma unroll
        for (int o = 16; o; o >>= 1) v = fmaxf(v, __shfl_down_sync(0xffffffffu, v, o));
        if (!lane) sh[0] = v;
    }
    __syncthreads();
    float r = sh[0]; __syncthreads(); return r;
}

// ---------------- GroupNorm -> token-major bf16 hT --------------
__global__ __launch_bounds__(256) void groupnorm_kernel(
    const float* __restrict__ x, const float* __restrict__ gamma,
    const float* __restrict__ beta, bf16* __restrict__ hT)
{
    __shared__ float sh[32];
    int b = blockIdx.x / GG, g = blockIdx.x % GG;
    const size_t base = ((size_t)b * Cc + (size_t)g * CPG) * NN;
    const long len = (long)CPG * NN;

    float s = 0.f, ss = 0.f;
    for (long i = threadIdx.x; i < len; i += 256) {
        float v = x[base + i]; s += v; ss += v * v;
    }
    s  = block_sum(s,  sh);
    ss = block_sum(ss, sh);
    float mean = s / (float)len;
    float var  = ss / (float)len - mean * mean;
    float inv  = rsqrtf(var + 1e-6f);

    float gm[CPG], bt[CPG];
    #pragma unroll
    for (int c = 0; c < CPG; c++) { gm[c] = gamma[g*CPG+c] * inv; bt[c] = beta[g*CPG+c]; }

    for (int i = threadIdx.x; i < NN; i += 256) {
        bf162 vals[CPG/2];
        #pragma unroll
        for (int c = 0; c < CPG; c += 2) {
            float a = (x[base + (size_t)c*NN + i] - mean) * gm[c] + bt[c];
            float b2 = (x[base + (size_t)(c+1)*NN + i] - mean) * gm[c+1] + bt[c+1];
            vals[c/2] = __floats2bfloat162_rn(a, b2);
        }
        bf16* dst = hT + ((size_t)b*NN + i) * Cc + g*CPG;
        #pragma unroll
        for (int q = 0; q < CPG/8; q++)
            ((float4*)dst)[q] = *(float4*)&vals[q*4];
    }
}

// ---------------- weight convert + bias concat ----------------
__global__ __launch_bounds__(256) void round_w_kernel(
    const float* __restrict__ a, const float* __restrict__ b,
    const float* __restrict__ c, const float* __restrict__ d,
    bf16* __restrict__ o)
{
    int i = blockIdx.x * 256 + threadIdx.x;
    int w = i >> 18, j = i & 0x3FFFF;
    const float* src = (w == 0) ? a : (w == 1) ? b : (w == 2) ? c : d;
    o[i] = __float2bfloat16_rn(src[j]);
}
__global__ __launch_bounds__(256) void concat_bias_kernel(
    const float* __restrict__ a, const float* __restrict__ b, float* __restrict__ o)
{
    int i = blockIdx.x * 256 + threadIdx.x;
    o[i] = (i < Cc) ? a[i] : b[i - Cc];
}

// ---------------- softmax: fp32 scores in -> bf16 attn out -------------
__global__ __launch_bounds__(256) void softmax_kernel(
    const float* __restrict__ s, bf16* __restrict__ a)
{
    __shared__ float sh[32];
    const float* p = s + (size_t)blockIdx.x * NN;
    bf16* pa = a + (size_t)blockIdx.x * NN;
    float v[16];
    #pragma unroll
    for (int t = 0; t < 16; t++) v[t] = p[threadIdx.x + t*256];
    float m = -INFINITY;
    #pragma unroll
    for (int t = 0; t < 16; t++) m = fmaxf(m, v[t]);
    m = block_max(m, sh);
    float sum = 0.f;
    #pragma unroll
    for (int t = 0; t < 16; t++) { v[t] = __expf(v[t] - m); sum += v[t]; }
    sum = block_sum(sum, sh);
    float inv = 1.f / sum;
    #pragma unroll
    for (int t = 0; t < 16; t++) pa[threadIdx.x + t*256] = __float2bfloat16_rn(v[t] * inv);
}

// ---------------- bf16 mma.sync GEMM: D[m,n] = Σk A[m,k] B[n,k] ----------
// CTA tile 128x128x64(bf16), 256 threads, warp grid 2(M)x4(N), warp tile 64x32.
// ldmatrix.x4 fragment loads (6 per k16), 3-stage cp.async, 2 CTAs/SM.
// EPI: 0 = +bias[n] -> bf16   (merged QK proj)
//      1 = +bias[m] -> bf16   (V proj)
//      2 = *alpha  -> fp32    (scores)
//      3 = -> bf16            (attn*V)
//      4 = +bias[m]+res fp32  (output proj + residual)
#define BM 128
#define BN 128
#define BK 64
#define STAGES 3
#define SROW 72                       // bf16 per smem row (144B, conflict-free ldmatrix)
#define ATILE_H (BM * SROW)
#define BTILE_H (BN * SROW)
#define STAGE_H (ATILE_H + BTILE_H)
#define STAGE_BYTES (STAGE_H * 2)
#define SMEM_REQ (STAGES * STAGE_BYTES)

template<int ROWS>
__device__ __forceinline__ void load_tile(const bf16* g, bf16* s, int tid, int ld) {
    int ch = tid & 7;
    int r0 = tid >> 3;
    #pragma unroll
    for (int i = 0; i < ROWS / 32; i++) {
        int r = r0 + i * 32;
        uint32_t dst = smem_u32(s + r * SROW + ch * 8);
        const bf16* src = g + (size_t)r * ld + ch * 8;
        asm volatile("cp.async.cg.shared.global [%0], [%1], 16;" :: "r"(dst), "l"(src));
    }
}

template<int EPI>
__global__ __launch_bounds__(256, 2) void mma_gemm(
    const bf16* __restrict__ A, long zA, int ldA,
    const bf16* __restrict__ B, long zB, int ldB,
    const float* __restrict__ bias,
    const float* __restrict__ res, long zR,
    void* __restrict__ Cout, long zC, int ldC,
    int K, float alpha)
{
    constexpr bool OUT_BF = (EPI == 0 || EPI == 1 || EPI == 3);
    extern __shared__ bf16 smem[];

    const int tid = threadIdx.x;
    const int m0 = blockIdx.y * BM, n0 = blockIdx.x * BN, bz = blockIdx.z;

    A += (size_t)bz * zA + (size_t)m0 * ldA;
    B += (size_t)bz * zB + (size_t)n0 * ldB;

    const int KT = K / BK;

    #pragma unroll
    for (int st = 0; st < STAGES - 1; st++) {
        load_tile<BM>(A + st * BK, smem + st * STAGE_H, tid, ldA);
        load_tile<BN>(B + st * BK, smem + st * STAGE_H + ATILE_H, tid, ldB);
        asm volatile("cp.async.commit_group;" ::: "memory");
    }

    const int lane = tid & 31, wid = tid >> 5;
    const int gid = lane >> 2, tig = lane & 3;
    const int wm = (wid & 1) * 64;
    const int wn = (wid >> 1) * 32;

    // ldmatrix lane->address maps (byte offsets within a stage)
    const uint32_t sbase = smem_u32(smem);
    // A: lanes 0-15 -> rows m0..15 @k0 ; lanes 16-31 -> rows m0..15 @k+8
    const uint32_t a_off = ((wm + (lane & 15)) * SROW + ((lane >> 4) * 8)) * 2;
    // B: n = (l&7) + ((l>>4)<<3) ; k = ((l>>3)&1)*8
    const uint32_t b_off = (ATILE_H + (wn + (lane & 7) + ((lane >> 4) << 3)) * SROW
                            + (((lane >> 3) & 1) * 8)) * 2;

    float c[4][4][4];
    #pragma unroll
    for (int im = 0; im < 4; im++)
        #pragma unroll
        for (int in = 0; in < 4; in++)
            #pragma unroll
            for (int r = 0; r < 4; r++) c[im][in][r] = 0.f;

    for (int kt = 0; kt < KT; kt++) {
        asm volatile("cp.async.wait_group %0;" :: "n"(STAGES - 2) : "memory");
        __syncthreads();

        if (kt + STAGES - 1 < KT) {
            int st = (kt + STAGES - 1) % STAGES;
            load_tile<BM>(A + (kt + STAGES - 1) * BK, smem + st * STAGE_H, tid, ldA);
            load_tile<BN>(B + (kt + STAGES - 1) * BK, smem + st * STAGE_H + ATILE_H, tid, ldB);
        }
        asm volatile("cp.async.commit_group;" ::: "memory");

        const uint32_t stb = sbase + (kt % STAGES) * STAGE_BYTES;

        #pragma unroll
        for (int kk = 0; kk < 4; kk++) {          // 4 x k16 per BK=64
            const uint32_t ka = stb + kk * 32;    // 16 bf16 = 32 bytes along k
            uint32_t af[4][4], bq[2][4];
            #pragma unroll
            for (int im = 0; im < 4; im++)
                ldmatrix_x4(af[im], ka + a_off + im * (16 * SROW * 2));
            #pragma unroll
            for (int ib = 0; ib < 2; ib++)
                ldmatrix_x4(bq[ib], ka + b_off + ib * (16 * SROW * 2));
            #pragma unroll
            for (int im = 0; im < 4; im++)
                #pragma unroll
                for (int in = 0; in < 4; in++)
                    mma_bf16(c[im][in], af[im], &bq[in >> 1][(in & 1) * 2]);
        }
        __syncthreads();
    }

    // ---- epilogue ----
    #pragma unroll
    for (int im = 0; im < 4; im++) {
        int r0 = im * 16 + gid;
        float bm0 = 0.f, bm1 = 0.f;
        if (EPI == 1 || EPI == 4) {
            bm0 = __ldg(bias + m0 + wm + r0);
            bm1 = __ldg(bias + m0 + wm + r0 + 8);
        }
        #pragma unroll
        for (int in = 0; in < 4; in++) {
            int col = in * 8 + tig * 2;
            float v0 = c[im][in][0], v1 = c[im][in][1];
            float v2 = c[im][in][2], v3 = c[im][in][3];
            if (EPI == 0) {
                float bn0 = __ldg(bias + n0 + wn + col);
                float bn1 = __ldg(bias + n0 + wn + col + 1);
                v0 += bn0; v1 += bn1; v2 += bn0; v3 += bn1;
            } else if (EPI == 1) {
                v0 += bm0; v1 += bm0; v2 += bm1; v3 += bm1;
            } else if (EPI == 2) {
                v0 *= alpha; v1 *= alpha; v2 *= alpha; v3 *= alpha;
            } else if (EPI == 4) {
                const float* ra = res + (size_t)bz * zR + (size_t)(m0 + wm + r0) * ldC + n0 + wn + col;
                const float* rb = res + (size_t)bz * zR + (size_t)(m0 + wm + r0 + 8) * ldC + n0 + wn + col;
                v0 += bm0 + ra[0]; v1 += bm0 + ra[1];
                v2 += bm1 + rb[0]; v3 += bm1 + rb[1];
            }
            if (OUT_BF) {
                bf16* Cb = (bf16*)Cout + (size_t)bz * zC + (size_t)(m0 + wm + r0) * ldC + n0 + wn + col;
                bf16* Cb2 = (bf16*)Cout + (size_t)bz * zC + (size_t)(m0 + wm + r0 + 8) * ldC + n0 + wn + col;
                *(bf162*)Cb  = __floats2bfloat162_rn(v0, v1);
                *(bf162*)Cb2 = __floats2bfloat162_rn(v2, v3);
            } else {
                float* Cf = (float*)Cout + (size_t)bz * zC + (size_t)(m0 + wm + r0) * ldC + n0 + wn + col;
                float* Cf2 = (float*)Cout + (size_t)bz * zC + (size_t)(m0 + wm + r0 + 8) * ldC + n0 + wn + col;
                *(float2*)Cf  = make_float2(v0, v1);
                *(float2*)Cf2 = make_float2(v2, v3);
            }
        }
    }
}

// ---------------- launch ----------------
extern "C" void kernel_launch(void* const* d_in, const int* in_sizes, int n_in,
                              void* d_out, int out_size)
{
    const float* x     = (const float*)d_in[0];
    const float* gamma = (const float*)d_in[1];
    const float* beta  = (const float*)d_in[2];
    const float* wq    = (const float*)d_in[3];
    const float* bq    = (const float*)d_in[4];
    const float* wk    = (const float*)d_in[5];
    const float* bk    = (const float*)d_in[6];
    const float* wv    = (const float*)d_in[7];
    const float* bv    = (const float*)d_in[8];
    const float* wo    = (const float*)d_in[9];
    const float* bo    = (const float*)d_in[10];
    float* out = (float*)d_out;

    bf16 *h16, *qk16, *v16, *ao16, *a16, *w16;
    float *s, *bqk;
    cudaGetSymbolAddress((void**)&h16,  g_h16);
    cudaGetSymbolAddress((void**)&qk16, g_qk16);
    cudaGetSymbolAddress((void**)&v16,  g_v16);
    cudaGetSymbolAddress((void**)&ao16, g_ao16);
    cudaGetSymbolAddress((void**)&a16,  g_a16);
    cudaGetSymbolAddress((void**)&w16,  g_w16);
    cudaGetSymbolAddress((void**)&s,    g_s);
    cudaGetSymbolAddress((void**)&bqk,  g_bqk);

    static bool attr_done = false;
    if (!attr_done) {
        cudaFuncSetAttribute(mma_gemm<0>, cudaFuncAttributeMaxDynamicSharedMemorySize, SMEM_REQ);
        cudaFuncSetAttribute(mma_gemm<1>, cudaFuncAttributeMaxDynamicSharedMemorySize, SMEM_REQ);
        cudaFuncSetAttribute(mma_gemm<2>, cudaFuncAttributeMaxDynamicSharedMemorySize, SMEM_REQ);
        cudaFuncSetAttribute(mma_gemm<3>, cudaFuncAttributeMaxDynamicSharedMemorySize, SMEM_REQ);
        cudaFuncSetAttribute(mma_gemm<4>, cudaFuncAttributeMaxDynamicSharedMemorySize, SMEM_REQ);
        attr_done = true;
    }

    const long CN  = (long)Cc * NN;      // [C,N] batch stride
    const long NC  = (long)NN * Cc;      // [N,C] batch stride
    const long NC2 = (long)NN * 2 * Cc;  // [N,2C] batch stride
    const long NN2 = (long)NN * NN;
    const float scale = 1.0f / sqrtf((float)Cc);

    // 1) GroupNorm -> h16 [B,N,C]
    groupnorm_kernel<<<Bb * GG, 256>>>(x, gamma, beta, h16);
    // 2) weights -> bf16, concat q/k biases
    round_w_kernel<<<4 * Cc * Cc / 256, 256>>>(wq, wk, wv, wo, w16);
    concat_bias_kernel<<<2 * Cc / 256, 256>>>(bq, bk, bqk);

    // 3) merged QK proj
    mma_gemm<0><<<dim3(2*Cc/BN, NN/BM, Bb), 256, SMEM_REQ>>>(
        h16, NC, Cc, w16, 0, Cc, bqk, nullptr, 0, qk16, NC2, 2*Cc, Cc, 0.f);
    // 4) V proj
    mma_gemm<1><<<dim3(NN/BN, Cc/BM, Bb), 256, SMEM_REQ>>>(
        w16 + 2*Cc*Cc, 0, Cc, h16, NC, Cc, bv, nullptr, 0, v16, CN, NN, Cc, 0.f);
    // 5) scores
    mma_gemm<2><<<dim3(NN/BN, NN/BM, Bb), 256, SMEM_REQ>>>(
        qk16, NC2, 2*Cc, qk16 + Cc, NC2, 2*Cc, nullptr, nullptr, 0, s, NN2, NN, Cc, scale);
    // 6) softmax
    softmax_kernel<<<Bb * NN, 256>>>(s, a16);
    // 7) attn * V
    mma_gemm<3><<<dim3(Cc/BN, NN/BM, Bb), 256, SMEM_REQ>>>(
        a16, NN2, NN, v16, CN, NN, nullptr, nullptr, 0, ao16, NC, Cc, NN, 0.f);
    // 8) output proj + residual
    mma_gemm<4><<<dim3(NN/BN, Cc/BM, Bb), 256, SMEM_REQ>>>(
        w16 + 3*Cc*Cc, 0, Cc, ao16, NC, Cc, bo, x, CN, out, CN, NN, Cc, 0.f);
}

// round 8
// speedup vs baseline: 1.9219x; 1.0256x over previous
#include <cuda_runtime.h>
#include <cuda_bf16.h>
#include <math.h>
#include <stdint.h>

typedef __nv_bfloat16 bf16;
typedef __nv_bfloat162 bf162;

// ---------------- problem constants ----------------
#define Bb 4
#define Cc 512
#define NN 4096
#define GG 32
#define CPG 16

// ---------------- scratch (device globals) ----------------
__device__ __align__(128) bf16  g_h16  [(size_t)Bb*NN*Cc];    // [B,N,C] GN out
__device__ __align__(128) bf16  g_qk16 [(size_t)Bb*NN*2*Cc];  // [B,N,2C] q|k
__device__ __align__(128) bf16  g_v16  [(size_t)Bb*Cc*NN];    // [B,C,N]
__device__ __align__(128) bf16  g_ao16 [(size_t)Bb*NN*Cc];    // [B,N,C]
__device__ __align__(128) float g_s    [(size_t)Bb*NN*NN];    // [B,N,N] scores fp32
__device__ __align__(128) bf16  g_a16  [(size_t)Bb*NN*NN];    // [B,N,N] attn bf16
__device__ __align__(128) bf16  g_w16  [4*Cc*Cc];             // wq|wk|wv|wo
__device__ __align__(128) float g_bqk  [2*Cc];                // bq|bk

// ---------------- helpers ----------------
__device__ __forceinline__ uint32_t smem_u32(const void* p) {
    uint32_t a;
    asm("{ .reg .u64 t; cvta.to.shared.u64 t, %1; cvt.u32.u64 %0, t; }" : "=r"(a) : "l"(p));
    return a;
}
__device__ __forceinline__ void mma_bf16(float* c, const uint32_t* a, const uint32_t* b) {
    asm volatile("mma.sync.aligned.m16n8k16.row.col.f32.bf16.bf16.f32 "
        "{%0,%1,%2,%3}, {%4,%5,%6,%7}, {%8,%9}, {%0,%1,%2,%3};"
        : "+f"(c[0]), "+f"(c[1]), "+f"(c[2]), "+f"(c[3])
        : "r"(a[0]), "r"(a[1]), "r"(a[2]), "r"(a[3]), "r"(b[0]), "r"(b[1]));
}
__device__ __forceinline__ void ldmatrix_x4(uint32_t* r, uint32_t addr) {
    asm volatile("ldmatrix.sync.aligned.m8n8.x4.shared.b16 {%0,%1,%2,%3}, [%4];"
        : "=r"(r[0]), "=r"(r[1]), "=r"(r[2]), "=r"(r[3]) : "r"(addr));
}

// ---------------- block reductions ----------------
__device__ __forceinline__ float block_sum(float v, float* sh) {
    int lane = threadIdx.x & 31, w = threadIdx.x >> 5;
    #pragma unroll
    for (int o = 16; o; o >>= 1) v += __shfl_down_sync(0xffffffffu, v, o);
    if (!lane) sh[w] = v;
    __syncthreads();
    int nw = blockDim.x >> 5;
    v = (threadIdx.x < nw) ? sh[threadIdx.x] : 0.f;
    if (w == 0) {
        #pragma unroll
        for (int o = 16; o; o >>= 1) v += __shfl_down_sync(0xffffffffu, v, o);
        if (!lane) sh[0] = v;
    }
    __syncthreads();
    float r = sh[0]; __syncthreads(); return r;
}
__device__ __forceinline__ float block_max(float v, float* sh) {
    int lane = threadIdx.x & 31, w = threadIdx.x >> 5;
    #pragma unroll
    for (int o = 16; o; o >>= 1) v = fmaxf(v, __shfl_down_sync(0xffffffffu, v, o));
    if (!lane) sh[w] = v;
    __syncthreads();
    int nw = blockDim.x >> 5;
    v = (threadIdx.x < nw) ? sh[threadIdx.x] : -INFINITY;
    if (w == 0) {
        #pragma unroll
        for (int o = 16; o; o >>= 1) v = fmaxf(v, __shfl_down_sync(0xffffffffu, v, o));
        if (!lane) sh[0] = v;
    }
    __syncthreads();
    float r = sh[0]; __syncthreads(); return r;
}

// ---------------- GroupNorm -> token-major bf16 hT --------------
__global__ __launch_bounds__(256) void groupnorm_kernel(
    const float* __restrict__ x, const float* __restrict__ gamma,
    const float* __restrict__ beta, bf16* __restrict__ hT)
{
    __shared__ float sh[32];
    int b = blockIdx.x / GG, g = blockIdx.x % GG;
    const size_t base = ((size_t)b * Cc + (size_t)g * CPG) * NN;
    const long len = (long)CPG * NN;

    float s = 0.f, ss = 0.f;
    for (long i = threadIdx.x; i < len; i += 256) {
        float v = x[base + i]; s += v; ss += v * v;
    }
    s  = block_sum(s,  sh);
    ss = block_sum(ss, sh);
    float mean = s / (float)len;
    float var  = ss / (float)len - mean * mean;
    float inv  = rsqrtf(var + 1e-6f);

    float gm[CPG], bt[CPG];
    #pragma unroll
    for (int c = 0; c < CPG; c++) { gm[c] = gamma[g*CPG+c] * inv; bt[c] = beta[g*CPG+c]; }

    for (int i = threadIdx.x; i < NN; i += 256) {
        bf162 vals[CPG/2];
        #pragma unroll
        for (int c = 0; c < CPG; c += 2) {
            float a = (x[base + (size_t)c*NN + i] - mean) * gm[c] + bt[c];
            float b2 = (x[base + (size_t)(c+1)*NN + i] - mean) * gm[c+1] + bt[c+1];
            vals[c/2] = __floats2bfloat162_rn(a, b2);
        }
        bf16* dst = hT + ((size_t)b*NN + i) * Cc + g*CPG;
        #pragma unroll
        for (int q = 0; q < CPG/8; q++)
            ((float4*)dst)[q] = *(float4*)&vals[q*4];
    }
}

// ---------------- weight convert + bias concat ----------------
__global__ __launch_bounds__(256) void round_w_kernel(
    const float* __restrict__ a, const float* __restrict__ b,
    const float* __restrict__ c, const float* __restrict__ d,
    bf16* __restrict__ o)
{
    int i = blockIdx.x * 256 + threadIdx.x;
    int w = i >> 18, j = i & 0x3FFFF;
    const float* src = (w == 0) ? a : (w == 1) ? b : (w == 2) ? c : d;
    o[i] = __float2bfloat16_rn(src[j]);
}
__global__ __launch_bounds__(256) void concat_bias_kernel(
    const float* __restrict__ a, const float* __restrict__ b, float* __restrict__ o)
{
    int i = blockIdx.x * 256 + threadIdx.x;
    o[i] = (i < Cc) ? a[i] : b[i - Cc];
}

// ---------------- softmax: fp32 scores in -> bf16 attn out -------------
__global__ __launch_bounds__(256) void softmax_kernel(
    const float* __restrict__ s, bf16* __restrict__ a)
{
    __shared__ float sh[32];
    const float* p = s + (size_t)blockIdx.x * NN;
    bf16* pa = a + (size_t)blockIdx.x * NN;
    float v[16];
    #pragma unroll
    for (int t = 0; t < 16; t++) v[t] = p[threadIdx.x + t*256];
    float m = -INFINITY;
    #pragma unroll
    for (int t = 0; t < 16; t++) m = fmaxf(m, v[t]);
    m = block_max(m, sh);
    float sum = 0.f;
    #pragma unroll
    for (int t = 0; t < 16; t++) { v[t] = __expf(v[t] - m); sum += v[t]; }
    sum = block_sum(sum, sh);
    float inv = 1.f / sum;
    #pragma unroll
    for (int t = 0; t < 16; t++) pa[threadIdx.x + t*256] = __float2bfloat16_rn(v[t] * inv);
}

// ---------------- bf16 mma.sync GEMM: D[m,n] = Σk A[m,k] B[n,k] ----------
// CTA tile 128x128x64(bf16), 256 threads, warp grid 2(M)x4(N), warp tile 64x32.
// ldmatrix.x4 frags with kk+1 double-buffer prefetch; SINGLE barrier per kt;
// 3-stage cp.async, 2 CTAs/SM.
// EPI: 0 = +bias[n] -> bf16   (merged QK proj)
//      1 = +bias[m] -> bf16   (V proj)
//      2 = *alpha  -> fp32    (scores)
//      3 = -> bf16            (attn*V)
//      4 = +bias[m]+res fp32  (output proj + residual)
#define BM 128
#define BN 128
#define BK 64
#define STAGES 3
#define SROW 72                       // bf16 per smem row (144B, conflict-free ldmatrix)
#define ATILE_H (BM * SROW)
#define BTILE_H (BN * SROW)
#define STAGE_H (ATILE_H + BTILE_H)
#define STAGE_BYTES (STAGE_H * 2)
#define SMEM_REQ (STAGES * STAGE_BYTES)

template<int ROWS>
__device__ __forceinline__ void load_tile(const bf16* g, bf16* s, int tid, int ld) {
    int ch = tid & 7;
    int r0 = tid >> 3;
    #pragma unroll
    for (int i = 0; i < ROWS / 32; i++) {
        int r = r0 + i * 32;
        uint32_t dst = smem_u32(s + r * SROW + ch * 8);
        const bf16* src = g + (size_t)r * ld + ch * 8;
        asm volatile("cp.async.cg.shared.global [%0], [%1], 16;" :: "r"(dst), "l"(src));
    }
}

template<int EPI>
__global__ __launch_bounds__(256, 2) void mma_gemm(
    const bf16* __restrict__ A, long zA, int ldA,
    const bf16* __restrict__ B, long zB, int ldB,
    const float* __restrict__ bias,
    const float* __restrict__ res, long zR,
    void* __restrict__ Cout, long zC, int ldC,
    int K, float alpha)
{
    constexpr bool OUT_BF = (EPI == 0 || EPI == 1 || EPI == 3);
    extern __shared__ bf16 smem[];

    const int tid = threadIdx.x;
    const int m0 = blockIdx.y * BM, n0 = blockIdx.x * BN, bz = blockIdx.z;

    A += (size_t)bz * zA + (size_t)m0 * ldA;
    B += (size_t)bz * zB + (size_t)n0 * ldB;

    const int KT = K / BK;

    #pragma unroll
    for (int st = 0; st < STAGES - 1; st++) {
        load_tile<BM>(A + st * BK, smem + st * STAGE_H, tid, ldA);
        load_tile<BN>(B + st * BK, smem + st * STAGE_H + ATILE_H, tid, ldB);
        asm volatile("cp.async.commit_group;" ::: "memory");
    }

    const int lane = tid & 31, wid = tid >> 5;
    const int gid = lane >> 2, tig = lane & 3;
    const int wm = (wid & 1) * 64;
    const int wn = (wid >> 1) * 32;

    const uint32_t sbase = smem_u32(smem);
    const uint32_t a_off = ((wm + (lane & 15)) * SROW + ((lane >> 4) * 8)) * 2;
    const uint32_t b_off = (ATILE_H + (wn + (lane & 7) + ((lane >> 4) << 3)) * SROW
                            + (((lane >> 3) & 1) * 8)) * 2;

    float c[4][4][4];
    #pragma unroll
    for (int im = 0; im < 4; im++)
        #pragma unroll
        for (int in = 0; in < 4; in++)
            #pragma unroll
            for (int r = 0; r < 4; r++) c[im][in][r] = 0.f;

    uint32_t af[2][4][4], bq[2][2][4];

    for (int kt = 0; kt < KT; kt++) {
        asm volatile("cp.async.wait_group %0;" :: "n"(STAGES - 2) : "memory");
        __syncthreads();   // single barrier per kt: orders compute(kt-1) before loads(kt)

        if (kt + STAGES - 1 < KT) {
            int st = (kt + STAGES - 1) % STAGES;
            load_tile<BM>(A + (kt + STAGES - 1) * BK, smem + st * STAGE_H, tid, ldA);
            load_tile<BN>(B + (kt + STAGES - 1) * BK, smem + st * STAGE_H + ATILE_H, tid, ldB);
        }
        asm volatile("cp.async.commit_group;" ::: "memory");

        const uint32_t stb = sbase + (kt % STAGES) * STAGE_BYTES;

        // prefetch kk=0 fragments
        #pragma unroll
        for (int im = 0; im < 4; im++)
            ldmatrix_x4(af[0][im], stb + a_off + im * (16 * SROW * 2));
        #pragma unroll
        for (int ib = 0; ib < 2; ib++)
            ldmatrix_x4(bq[0][ib], stb + b_off + ib * (16 * SROW * 2));

        #pragma unroll
        for (int kk = 0; kk < 4; kk++) {          // 4 x k16 per BK=64
            int cur = kk & 1, nxt = cur ^ 1;
            if (kk < 3) {
                const uint32_t ka = stb + (kk + 1) * 32;
                #pragma unroll
                for (int im = 0; im < 4; im++)
                    ldmatrix_x4(af[nxt][im], ka + a_off + im * (16 * SROW * 2));
                #pragma unroll
                for (int ib = 0; ib < 2; ib++)
                    ldmatrix_x4(bq[nxt][ib], ka + b_off + ib * (16 * SROW * 2));
            }
            #pragma unroll
            for (int im = 0; im < 4; im++)
                #pragma unroll
                for (int in = 0; in < 4; in++)
                    mma_bf16(c[im][in], af[cur][im], &bq[cur][in >> 1][(in & 1) * 2]);
        }
        // no trailing barrier: top-of-loop barrier provides the ordering
    }

    // ---- epilogue ----
    #pragma unroll
    for (int im = 0; im < 4; im++) {
        int r0 = im * 16 + gid;
        float bm0 = 0.f, bm1 = 0.f;
        if (EPI == 1 || EPI == 4) {
            bm0 = __ldg(bias + m0 + wm + r0);
            bm1 = __ldg(bias + m0 + wm + r0 + 8);
        }
        #pragma unroll
        for (int in = 0; in < 4; in++) {
            int col = in * 8 + tig * 2;
            float v0 = c[im][in][0], v1 = c[im][in][1];
            float v2 = c[im][in][2], v3 = c[im][in][3];
            if (EPI == 0) {
                float bn0 = __ldg(bias + n0 + wn + col);
                float bn1 = __ldg(bias + n0 + wn + col + 1);
                v0 += bn0; v1 += bn1; v2 += bn0; v3 += bn1;
            } else if (EPI == 1) {
                v0 += bm0; v1 += bm0; v2 += bm1; v3 += bm1;
            } else if (EPI == 2) {
                v0 *= alpha; v1 *= alpha; v2 *= alpha; v3 *= alpha;
            } else if (EPI == 4) {
                const float* ra = res + (size_t)bz * zR + (size_t)(m0 + wm + r0) * ldC + n0 + wn + col;
                const float* rb = res + (size_t)bz * zR + (size_t)(m0 + wm + r0 + 8) * ldC + n0 + wn + col;
                v0 += bm0 + ra[0]; v1 += bm0 + ra[1];
                v2 += bm1 + rb[0]; v3 += bm1 + rb[1];
            }
            if (OUT_BF) {
                bf16* Cb = (bf16*)Cout + (size_t)bz * zC + (size_t)(m0 + wm + r0) * ldC + n0 + wn + col;
                bf16* Cb2 = (bf16*)Cout + (size_t)bz * zC + (size_t)(m0 + wm + r0 + 8) * ldC + n0 + wn + col;
                *(bf162*)Cb  = __floats2bfloat162_rn(v0, v1);
                *(bf162*)Cb2 = __floats2bfloat162_rn(v2, v3);
            } else {
                float* Cf = (float*)Cout + (size_t)bz * zC + (size_t)(m0 + wm + r0) * ldC + n0 + wn + col;
                float* Cf2 = (float*)Cout + (size_t)bz * zC + (size_t)(m0 + wm + r0 + 8) * ldC + n0 + wn + col;
                *(float2*)Cf  = make_float2(v0, v1);
                *(float2*)Cf2 = make_float2(v2, v3);
            }
        }
    }
}

// ---------------- launch ----------------
extern "C" void kernel_launch(void* const* d_in, const int* in_sizes, int n_in,
                              void* d_out, int out_size)
{
    const float* x     = (const float*)d_in[0];
    const float* gamma = (const float*)d_in[1];
    const float* beta  = (const float*)d_in[2];
    const float* wq    = (const float*)d_in[3];
    const float* bq    = (const float*)d_in[4];
    const float* wk    = (const float*)d_in[5];
    const float* bk    = (const float*)d_in[6];
    const float* wv    = (const float*)d_in[7];
    const float* bv    = (const float*)d_in[8];
    const float* wo    = (const float*)d_in[9];
    const float* bo    = (const float*)d_in[10];
    float* out = (float*)d_out;

    bf16 *h16, *qk16, *v16, *ao16, *a16, *w16;
    float *s, *bqk;
    cudaGetSymbolAddress((void**)&h16,  g_h16);
    cudaGetSymbolAddress((void**)&qk16, g_qk16);
    cudaGetSymbolAddress((void**)&v16,  g_v16);
    cudaGetSymbolAddress((void**)&ao16, g_ao16);
    cudaGetSymbolAddress((void**)&a16,  g_a16);
    cudaGetSymbolAddress((void**)&w16,  g_w16);
    cudaGetSymbolAddress((void**)&s,    g_s);
    cudaGetSymbolAddress((void**)&bqk,  g_bqk);

    static bool attr_done = false;
    if (!attr_done) {
        cudaFuncSetAttribute(mma_gemm<0>, cudaFuncAttributeMaxDynamicSharedMemorySize, SMEM_REQ);
        cudaFuncSetAttribute(mma_gemm<1>, cudaFuncAttributeMaxDynamicSharedMemorySize, SMEM_REQ);
        cudaFuncSetAttribute(mma_gemm<2>, cudaFuncAttributeMaxDynamicSharedMemorySize, SMEM_REQ);
        cudaFuncSetAttribute(mma_gemm<3>, cudaFuncAttributeMaxDynamicSharedMemorySize, SMEM_REQ);
        cudaFuncSetAttribute(mma_gemm<4>, cudaFuncAttributeMaxDynamicSharedMemorySize, SMEM_REQ);
        attr_done = true;
    }

    const long CN  = (long)Cc * NN;      // [C,N] batch stride
    const long NC  = (long)NN * Cc;      // [N,C] batch stride
    const long NC2 = (long)NN * 2 * Cc;  // [N,2C] batch stride
    const long NN2 = (long)NN * NN;
    const float scale = 1.0f / sqrtf((float)Cc);

    // 1) GroupNorm -> h16 [B,N,C]
    groupnorm_kernel<<<Bb * GG, 256>>>(x, gamma, beta, h16);
    // 2) weights -> bf16, concat q/k biases
    round_w_kernel<<<4 * Cc * Cc / 256, 256>>>(wq, wk, wv, wo, w16);
    concat_bias_kernel<<<2 * Cc / 256, 256>>>(bq, bk, bqk);

    // 3) merged QK proj
    mma_gemm<0><<<dim3(2*Cc/BN, NN/BM, Bb), 256, SMEM_REQ>>>(
        h16, NC, Cc, w16, 0, Cc, bqk, nullptr, 0, qk16, NC2, 2*Cc, Cc, 0.f);
    // 4) V proj
    mma_gemm<1><<<dim3(NN/BN, Cc/BM, Bb), 256, SMEM_REQ>>>(
        w16 + 2*Cc*Cc, 0, Cc, h16, NC, Cc, bv, nullptr, 0, v16, CN, NN, Cc, 0.f);
    // 5) scores
    mma_gemm<2><<<dim3(NN/BN, NN/BM, Bb), 256, SMEM_REQ>>>(
        qk16, NC2, 2*Cc, qk16 + Cc, NC2, 2*Cc, nullptr, nullptr, 0, s, NN2, NN, Cc, scale);
    // 6) softmax
    softmax_kernel<<<Bb * NN, 256>>>(s, a16);
    // 7) attn * V
    mma_gemm<3><<<dim3(Cc/BN, NN/BM, Bb), 256, SMEM_REQ>>>(
        a16, NN2, NN, v16, CN, NN, nullptr, nullptr, 0, ao16, NC, Cc, NN, 0.f);
    // 8) output proj + residual
    mma_gemm<4><<<dim3(NN/BN, Cc/BM, Bb), 256, SMEM_REQ>>>(
        w16 + 3*Cc*Cc, 0, Cc, ao16, NC, Cc, bo, x, CN, out, CN, NN, Cc, 0.f);
}